// round 10
// baseline (speedup 1.0000x reference)
#include <cuda_runtime.h>

namespace {
constexpr int T_STEPS = 256;
constexpr int B_SZ    = 4096;
constexpr int HID     = 64;
constexpr int MLPW    = 128;
constexpr int DOUT    = 8;
constexpr int R4      = 4;            // rows per warp
constexpr int P8      = 8;            // drift/diff pairs per CTA
constexpr int NWARPS  = 16;
constexpr int NSTEP   = 255;
constexpr int NCTA    = 128;          // 128 * 8 * 4 = 4096 rows exactly
}

using ull = unsigned long long;

// ---- packed weight scratch (written by pack_weights, read by sde_kernel) ----
// layout: p[((kb*N)+n)*4 + j] = W[(4kb+j)+rowoff][n]
__device__ float wpD0[64 * 128];
__device__ float wpD1[128 * 128];
__device__ float wpDo[128 * 64];
__device__ float wpF0[64 * 128];
__device__ float wpF1[128 * 128];
__device__ float wpFo[128 * 64];

__global__ void pack_weights(const float* __restrict__ dW0, const float* __restrict__ dW1,
                             const float* __restrict__ dWo, const float* __restrict__ fW0,
                             const float* __restrict__ fW1, const float* __restrict__ fWo)
{
    int e = blockIdx.x * blockDim.x + threadIdx.x;   // 0..65535
    if (e >= 65536) return;
    int m = e >> 15;           // 0 = drift, 1 = diff
    int i = e & 32767;
    const float* W; float* dst; int N, rowoff, base;
    if (i < 8192)        { W = m ? fW0 : dW0; dst = m ? wpF0 : wpD0; N = 128; rowoff = 1; base = i; }
    else if (i < 24576)  { W = m ? fW1 : dW1; dst = m ? wpF1 : wpD1; N = 128; rowoff = 0; base = i - 8192; }
    else                 { W = m ? fWo : dWo; dst = m ? wpFo : wpDo; N = 64;  rowoff = 0; base = i - 24576; }
    int kb  = base / (N * 4);
    int rem = base % (N * 4);
    int n   = rem >> 2;
    int j   = rem & 3;
    dst[base] = W[(4 * kb + j + rowoff) * N + n];
}

// ---- helpers ----
__device__ __forceinline__ ull fma2(ull a, ull b, ull c) {
    ull d; asm("fma.rn.f32x2 %0, %1, %2, %3;" : "=l"(d) : "l"(a), "l"(b), "l"(c)); return d;
}
__device__ __forceinline__ ull pack2(float lo, float hi) {
    ull d; unsigned a = __float_as_uint(lo), b = __float_as_uint(hi);
    asm("mov.b64 %0, {%1, %2};" : "=l"(d) : "r"(a), "r"(b)); return d;
}
__device__ __forceinline__ float2 unpack2(ull v) {
    float2 r; asm("mov.b64 {%0, %1}, %2;" : "=f"(r.x), "=f"(r.y) : "l"(v)); return r;
}
__device__ __forceinline__ float lipswish(float x) {
    float s = 1.0f / (1.0f + __expf(-x)); return 0.909f * x * s;
}
__device__ __forceinline__ void pair_sync(int q) {
    asm volatile("bar.sync %0, 64;" :: "r"(q + 1) : "memory");
}

struct QShm {                      // one drift/diff pair (8 KB)
    float aIn[R4][HID];            // zhat (gemm input), compact
    float hD [R4][MLPW];           // drift MLP scratch / readout z staging
    float hF [R4][MLPW];           // diff MLP scratch
    float gEx[R4][HID];            // g exchange
    float dwS[2][R4][HID];         // sqrt(dt)*dW double buffer
};

// k-packed gemm, N=128: acc[r][g] is f32x2 (even-k, odd-k partial sums),
// lane owns cols n = lane + 32g. aIn compact [R4][K], broadcast reads.
template<int K>
__device__ __forceinline__ void gemm_kp128(const float* __restrict__ Wp,
                                           const float* __restrict__ aIn,
                                           ull acc[R4][4], int lane)
{
#pragma unroll 4
    for (int kb = 0; kb < K / 4; kb++) {
        ulonglong2 w[4];
#pragma unroll
        for (int g = 0; g < 4; g++)
            w[g] = __ldg(reinterpret_cast<const ulonglong2*>(
                       Wp + (size_t)(kb * 128 + lane + 32 * g) * 4));
#pragma unroll
        for (int r = 0; r < R4; r++) {
            ulonglong2 a = *reinterpret_cast<const ulonglong2*>(aIn + r * K + kb * 4);
#pragma unroll
            for (int g = 0; g < 4; g++) {
                acc[r][g] = fma2(a.x, w[g].x, acc[r][g]);
                acc[r][g] = fma2(a.y, w[g].y, acc[r][g]);
            }
        }
    }
}

// k-packed gemm, N=64: lane owns cols n = lane + 32g, g<2.
template<int K>
__device__ __forceinline__ void gemm_kp64(const float* __restrict__ Wp,
                                          const float* __restrict__ aIn,
                                          ull acc[R4][2], int lane)
{
#pragma unroll 4
    for (int kb = 0; kb < K / 4; kb++) {
        ulonglong2 w[2];
#pragma unroll
        for (int g = 0; g < 2; g++)
            w[g] = __ldg(reinterpret_cast<const ulonglong2*>(
                       Wp + (size_t)(kb * 64 + lane + 32 * g) * 4));
#pragma unroll
        for (int r = 0; r < R4; r++) {
            ulonglong2 a = *reinterpret_cast<const ulonglong2*>(aIn + r * K + kb * 4);
#pragma unroll
            for (int g = 0; g < 2; g++) {
                acc[r][g] = fma2(a.x, w[g].x, acc[r][g]);
                acc[r][g] = fma2(a.y, w[g].y, acc[r][g]);
            }
        }
    }
}

// Full MLP for 4 rows: [t, x(64)] -> lipswish -> lipswish -> tanh.
// outv[r][j] for hidden col = lane + 32j.
__device__ __forceinline__ void mlp_kp(
    float tn,
    const float* __restrict__ Wp0, const float* __restrict__ W0row0,
    const float* __restrict__ b0,
    const float* __restrict__ Wp1, const float* __restrict__ b1,
    const float* __restrict__ Wpo, const float* __restrict__ bo,
    const float* __restrict__ aIn,  // [R4][HID] zhat, compact
    float* __restrict__ hS,         // [R4][MLPW] scratch (in-place h1->h2)
    float outv[R4][2], int lane)
{
    ull acc[R4][4];
    {   // init: bias + t * W0_row0 in the even slot, 0 in odd
#pragma unroll
        for (int g = 0; g < 4; g++) {
            float b = __ldg(b0 + lane + 32 * g);
            float w = __ldg(W0row0 + lane + 32 * g);
            ull init = pack2(fmaf(tn, w, b), 0.0f);
#pragma unroll
            for (int r = 0; r < R4; r++) acc[r][g] = init;
        }
    }
    gemm_kp128<HID>(Wp0, aIn, acc, lane);
#pragma unroll
    for (int r = 0; r < R4; r++)
#pragma unroll
        for (int g = 0; g < 4; g++) {
            float2 v = unpack2(acc[r][g]);
            hS[r * MLPW + lane + 32 * g] = lipswish(v.x + v.y);
        }
    __syncwarp();

    {
#pragma unroll
        for (int g = 0; g < 4; g++) {
            ull init = pack2(__ldg(b1 + lane + 32 * g), 0.0f);
#pragma unroll
            for (int r = 0; r < R4; r++) acc[r][g] = init;
        }
    }
    gemm_kp128<MLPW>(Wp1, hS, acc, lane);
    __syncwarp();   // all lanes done reading h1 before in-place overwrite
#pragma unroll
    for (int r = 0; r < R4; r++)
#pragma unroll
        for (int g = 0; g < 4; g++) {
            float2 v = unpack2(acc[r][g]);
            hS[r * MLPW + lane + 32 * g] = lipswish(v.x + v.y);
        }
    __syncwarp();

    ull acc2[R4][2];
    {
#pragma unroll
        for (int g = 0; g < 2; g++) {
            ull init = pack2(__ldg(bo + lane + 32 * g), 0.0f);
#pragma unroll
            for (int r = 0; r < R4; r++) acc2[r][g] = init;
        }
    }
    gemm_kp64<MLPW>(Wpo, hS, acc2, lane);
#pragma unroll
    for (int r = 0; r < R4; r++)
#pragma unroll
        for (int j = 0; j < 2; j++) {
            float2 v = unpack2(acc2[r][j]);
            outv[r][j] = tanhf(v.x + v.y);
        }
}

// Drift warp: stage z into zc (reuses hD), then one pass of 4-rows readout.
__device__ __forceinline__ void readout_kp(
    const float zz[R4][2], float* __restrict__ zc,
    const float (*sRWt)[68], const float* __restrict__ sRB,
    float* __restrict__ out, int rowbase, int tIdx, float tval, int lane)
{
#pragma unroll
    for (int r = 0; r < R4; r++) {
        zc[r * HID + lane]      = zz[r][0];
        zc[r * HID + lane + 32] = zz[r][1];
    }
    __syncwarp();
    const int d = lane & 7;
    const int r = lane >> 3;
    float acc = sRB[d];
#pragma unroll
    for (int hb = 0; hb < HID / 4; hb++) {
        float4 zv = *reinterpret_cast<const float4*>(zc + r * HID + hb * 4);
        float4 wv = *reinterpret_cast<const float4*>(&sRWt[d][hb * 4]);
        acc = fmaf(zv.x, wv.x, acc);
        acc = fmaf(zv.y, wv.y, acc);
        acc = fmaf(zv.z, wv.z, acc);
        acc = fmaf(zv.w, wv.w, acc);
    }
    size_t base = ((size_t)(rowbase + r) * T_STEPS + tIdx) * (DOUT + 1);
    out[base + 1 + d] = acc;
    if (d == 0) out[base] = tval;
    __syncwarp();   // zc (hD) reads done before next MLP reuses it
}

__global__ void __launch_bounds__(NWARPS * 32, 1)
sde_kernel(const float* __restrict__ ts,
           const float* __restrict__ dW,
           const float* __restrict__ dW0, const float* __restrict__ db0,
           const float* __restrict__ db1, const float* __restrict__ dbo,
           const float* __restrict__ fW0, const float* __restrict__ fb0,
           const float* __restrict__ fb1, const float* __restrict__ fbo,
           const float* __restrict__ RW, const float* __restrict__ rb,
           float* __restrict__ out)
{
    extern __shared__ char dyn[];
    QShm* Q = reinterpret_cast<QShm*>(dyn);
    float (*sRWt)[68] = reinterpret_cast<float(*)[68]>(dyn + P8 * sizeof(QShm));
    float* sRB = reinterpret_cast<float*>(dyn + P8 * sizeof(QShm) + DOUT * 68 * sizeof(float));

    const int tid  = threadIdx.x;
    const int w    = tid >> 5;
    const int lane = tid & 31;
    const int q    = w >> 1;
    const bool isDrift = (w & 1) == 0;
    QShm& S = Q[q];
    float* hS = isDrift ? &S.hD[0][0] : &S.hF[0][0];
    const int rowbase = (blockIdx.x * P8 + q) * R4;

    for (int i = tid; i < HID * DOUT; i += blockDim.x)
        sRWt[i & 7][i >> 3] = __ldg(RW + i);        // RW is (64, 8) row-major
    if (tid < DOUT) sRB[tid] = __ldg(rb + tid);

    const float t0  = __ldg(ts + 0);
    const float dt  = __ldg(ts + 1) - t0;
    const float sdt = sqrtf(dt);

    const float* Wp0 = isDrift ? wpD0 : wpF0;
    const float* Wp1 = isDrift ? wpD1 : wpF1;
    const float* Wpo = isDrift ? wpDo : wpFo;
    const float* W0r = isDrift ? dW0  : fW0;   // row 0 = t weights
    const float* b0  = isDrift ? db0  : fb0;
    const float* b1  = isDrift ? db1  : fb1;
    const float* bo  = isDrift ? dbo  : fbo;

    float zz[R4][2], zh[R4][2], ff[R4][2], gg[R4][2], res[R4][2];

    if (isDrift) {
#pragma unroll
        for (int r = 0; r < R4; r++) {
            zz[r][0] = zz[r][1] = 1.0f;
            zh[r][0] = zh[r][1] = 1.0f;
            S.aIn[r][lane]      = 1.0f;
            S.aIn[r][lane + 32] = 1.0f;
        }
    } else {
        // stage sqrt(dt)*dW for step 0 into buffer 0
#pragma unroll
        for (int r = 0; r < R4; r++) {
            float a = __ldg(dW + (size_t)(rowbase + r) * HID + lane);
            float b = __ldg(dW + (size_t)(rowbase + r) * HID + lane + 32);
            S.dwS[0][r][lane]      = a * sdt;
            S.dwS[0][r][lane + 32] = b * sdt;
        }
    }
    __syncthreads();   // sRWt + initial staging visible block-wide (once)

    // f0 / g0 at t = ts[0], x0 = ones
    mlp_kp(t0, Wp0, W0r, b0, Wp1, b1, Wpo, bo, &S.aIn[0][0], hS, res, lane);
    if (!isDrift) {
#pragma unroll
        for (int r = 0; r < R4; r++) {
            S.gEx[r][lane]      = res[r][0];
            S.gEx[r][lane + 32] = res[r][1];
        }
    }
    pair_sync(q);

    if (isDrift) {
#pragma unroll
        for (int r = 0; r < R4; r++) {
            ff[r][0] = res[r][0]; ff[r][1] = res[r][1];
            gg[r][0] = S.gEx[r][lane];
            gg[r][1] = S.gEx[r][lane + 32];
        }
        readout_kp(zz, &S.hD[0][0], sRWt, sRB, out, rowbase, 0, t0, lane); // z = ones
    }

    for (int n = 0; n < NSTEP; n++) {
        const float tn = __ldg(ts + n + 1);

        if (isDrift) {
            // zhat_{n+1} = 2z - zhat + f dt + g dw ; stage compact
#pragma unroll
            for (int r = 0; r < R4; r++) {
#pragma unroll
                for (int j = 0; j < 2; j++) {
                    float dw = S.dwS[n & 1][r][lane + 32 * j];
                    float t1 = fmaf(2.0f, zz[r][j], -zh[r][j]);
                    t1 = fmaf(ff[r][j], dt, t1);
                    zh[r][j] = fmaf(gg[r][j], dw, t1);
                    S.aIn[r][lane + 32 * j] = zh[r][j];
                }
            }
        }
        pair_sync(q);      // B1: aIn ready

        mlp_kp(tn, Wp0, W0r, b0, Wp1, b1, Wpo, bo, &S.aIn[0][0], hS, res, lane);

        if (!isDrift) {
#pragma unroll
            for (int r = 0; r < R4; r++) {
                S.gEx[r][lane]      = res[r][0];
                S.gEx[r][lane + 32] = res[r][1];
            }
            // stage next step's Brownian increments into the other buffer
            const int m = (n + 1 < NSTEP) ? (n + 1) : (NSTEP - 1);
#pragma unroll
            for (int r = 0; r < R4; r++) {
                float a = __ldg(dW + ((size_t)m * B_SZ + rowbase + r) * HID + lane);
                float b = __ldg(dW + ((size_t)m * B_SZ + rowbase + r) * HID + lane + 32);
                S.dwS[(n + 1) & 1][r][lane]      = a * sdt;
                S.dwS[(n + 1) & 1][r][lane + 32] = b * sdt;
            }
        }
        pair_sync(q);      // B2: gEx (and next dwS) ready

        if (isDrift) {
#pragma unroll
            for (int r = 0; r < R4; r++) {
#pragma unroll
                for (int j = 0; j < 2; j++) {
                    float gn = S.gEx[r][lane + 32 * j];
                    float dw = S.dwS[n & 1][r][lane + 32 * j];
                    float fn = res[r][j];
                    zz[r][j] = fmaf(0.5f * (ff[r][j] + fn), dt, zz[r][j]);
                    zz[r][j] = fmaf(0.5f * (gg[r][j] + gn), dw, zz[r][j]);
                    ff[r][j] = fn;
                    gg[r][j] = gn;
                }
            }
            readout_kp(zz, &S.hD[0][0], sRWt, sRB, out, rowbase, n + 1, tn, lane);
        }
    }
}

extern "C" void kernel_launch(void* const* d_in, const int* in_sizes, int n_in,
                              void* d_out, int out_size) {
    (void)in_sizes; (void)n_in; (void)out_size;
    const float* ts  = (const float*)d_in[0];
    // d_in[1] = batch_size (int32 scalar) — shapes are fixed constants here
    const float* dW  = (const float*)d_in[2];
    const float* dW0 = (const float*)d_in[3];
    const float* db0 = (const float*)d_in[4];
    const float* dW1 = (const float*)d_in[5];
    const float* db1 = (const float*)d_in[6];
    const float* dWo = (const float*)d_in[7];
    const float* dbo = (const float*)d_in[8];
    const float* fW0 = (const float*)d_in[9];
    const float* fb0 = (const float*)d_in[10];
    const float* fW1 = (const float*)d_in[11];
    const float* fb1 = (const float*)d_in[12];
    const float* fWo = (const float*)d_in[13];
    const float* fbo = (const float*)d_in[14];
    const float* RW  = (const float*)d_in[15];
    const float* rb  = (const float*)d_in[16];
    float* out = (float*)d_out;

    pack_weights<<<256, 256>>>(dW0, dW1, dWo, fW0, fW1, fWo);

    const int smem = P8 * (int)sizeof(QShm) + DOUT * 68 * (int)sizeof(float) + 64;
    cudaFuncSetAttribute(sde_kernel, cudaFuncAttributeMaxDynamicSharedMemorySize, smem);

    sde_kernel<<<NCTA, NWARPS * 32, smem>>>(ts, dW,
                                            dW0, db0, db1, dbo,
                                            fW0, fb0, fb1, fbo,
                                            RW, rb, out);
}

// round 11
// speedup vs baseline: 1.0024x; 1.0024x over previous
#include <cuda_runtime.h>

namespace {
constexpr int T_STEPS = 256;
constexpr int B_SZ    = 4096;
constexpr int HID     = 64;
constexpr int MLPW    = 128;
constexpr int DOUT    = 8;
constexpr int R4      = 4;            // rows per warp
constexpr int P8      = 8;            // drift/diff pairs per CTA
constexpr int NWARPS  = 16;
constexpr int NSTEP   = 255;
constexpr int NCTA    = 128;          // 128 * 8 * 4 = 4096 rows exactly
}

using ull = unsigned long long;

// ---- packed weight scratch (written by pack_weights, read by sde_kernel) ----
// layout: p[((kb*N)+n)*4 + j] = W[(4kb+j)+rowoff][n]
__device__ float wpD0[64 * 128];
__device__ float wpD1[128 * 128];
__device__ float wpDo[128 * 64];
__device__ float wpF0[64 * 128];
__device__ float wpF1[128 * 128];
__device__ float wpFo[128 * 64];

__global__ void pack_weights(const float* __restrict__ dW0, const float* __restrict__ dW1,
                             const float* __restrict__ dWo, const float* __restrict__ fW0,
                             const float* __restrict__ fW1, const float* __restrict__ fWo)
{
    int e = blockIdx.x * blockDim.x + threadIdx.x;   // 0..65535
    if (e >= 65536) return;
    int m = e >> 15;           // 0 = drift, 1 = diff
    int i = e & 32767;
    const float* W; float* dst; int N, rowoff, base;
    if (i < 8192)        { W = m ? fW0 : dW0; dst = m ? wpF0 : wpD0; N = 128; rowoff = 1; base = i; }
    else if (i < 24576)  { W = m ? fW1 : dW1; dst = m ? wpF1 : wpD1; N = 128; rowoff = 0; base = i - 8192; }
    else                 { W = m ? fWo : dWo; dst = m ? wpFo : wpDo; N = 64;  rowoff = 0; base = i - 24576; }
    int kb  = base / (N * 4);
    int rem = base % (N * 4);
    int n   = rem >> 2;
    int j   = rem & 3;
    dst[base] = W[(4 * kb + j + rowoff) * N + n];
}

// ---- helpers ----
__device__ __forceinline__ ull fma2(ull a, ull b, ull c) {
    ull d; asm("fma.rn.f32x2 %0, %1, %2, %3;" : "=l"(d) : "l"(a), "l"(b), "l"(c)); return d;
}
__device__ __forceinline__ ull pack2(float lo, float hi) {
    ull d; unsigned a = __float_as_uint(lo), b = __float_as_uint(hi);
    asm("mov.b64 %0, {%1, %2};" : "=l"(d) : "r"(a), "r"(b)); return d;
}
__device__ __forceinline__ float2 unpack2(ull v) {
    float2 r; asm("mov.b64 {%0, %1}, %2;" : "=f"(r.x), "=f"(r.y) : "l"(v)); return r;
}
__device__ __forceinline__ float lipswish(float x) {
    float s = 1.0f / (1.0f + __expf(-x)); return 0.909f * x * s;
}
__device__ __forceinline__ void pair_sync(int q) {
    asm volatile("bar.sync %0, 64;" :: "r"(q + 1) : "memory");
}

struct QShm {                      // one drift/diff pair (8 KB)
    float aIn[R4][HID];            // zhat (gemm input), compact
    float hD [R4][MLPW];           // drift MLP scratch / readout z staging
    float hF [R4][MLPW];           // diff MLP scratch
    float gEx[R4][HID];            // g exchange
    float dwS[2][R4][HID];         // sqrt(dt)*dW double buffer
};

// k-packed gemm, N=128: acc[r][g] is f32x2 (even-k, odd-k partial sums),
// lane owns cols n = lane + 32g. aIn compact [R4][K], broadcast reads.
template<int K>
__device__ __forceinline__ void gemm_kp128(const float* __restrict__ Wp,
                                           const float* __restrict__ aIn,
                                           ull acc[R4][4], int lane)
{
#pragma unroll 4
    for (int kb = 0; kb < K / 4; kb++) {
        ulonglong2 w[4];
#pragma unroll
        for (int g = 0; g < 4; g++)
            w[g] = __ldg(reinterpret_cast<const ulonglong2*>(
                       Wp + (size_t)(kb * 128 + lane + 32 * g) * 4));
#pragma unroll
        for (int r = 0; r < R4; r++) {
            ulonglong2 a = *reinterpret_cast<const ulonglong2*>(aIn + r * K + kb * 4);
#pragma unroll
            for (int g = 0; g < 4; g++) {
                acc[r][g] = fma2(a.x, w[g].x, acc[r][g]);
                acc[r][g] = fma2(a.y, w[g].y, acc[r][g]);
            }
        }
    }
}

// k-packed gemm, N=64: lane owns cols n = lane + 32g, g<2.
template<int K>
__device__ __forceinline__ void gemm_kp64(const float* __restrict__ Wp,
                                          const float* __restrict__ aIn,
                                          ull acc[R4][2], int lane)
{
#pragma unroll 4
    for (int kb = 0; kb < K / 4; kb++) {
        ulonglong2 w[2];
#pragma unroll
        for (int g = 0; g < 2; g++)
            w[g] = __ldg(reinterpret_cast<const ulonglong2*>(
                       Wp + (size_t)(kb * 64 + lane + 32 * g) * 4));
#pragma unroll
        for (int r = 0; r < R4; r++) {
            ulonglong2 a = *reinterpret_cast<const ulonglong2*>(aIn + r * K + kb * 4);
#pragma unroll
            for (int g = 0; g < 2; g++) {
                acc[r][g] = fma2(a.x, w[g].x, acc[r][g]);
                acc[r][g] = fma2(a.y, w[g].y, acc[r][g]);
            }
        }
    }
}

// Full MLP for 4 rows: [t, x(64)] -> lipswish -> lipswish -> tanh.
// outv[r][j] for hidden col = lane + 32j.
__device__ __forceinline__ void mlp_kp(
    float tn,
    const float* __restrict__ Wp0, const float* __restrict__ W0row0,
    const float* __restrict__ b0,
    const float* __restrict__ Wp1, const float* __restrict__ b1,
    const float* __restrict__ Wpo, const float* __restrict__ bo,
    const float* __restrict__ aIn,  // [R4][HID] zhat, compact
    float* __restrict__ hS,         // [R4][MLPW] scratch (in-place h1->h2)
    float outv[R4][2], int lane)
{
    ull acc[R4][4];
    {   // init: bias + t * W0_row0 in the even slot, 0 in odd
#pragma unroll
        for (int g = 0; g < 4; g++) {
            float b = __ldg(b0 + lane + 32 * g);
            float w = __ldg(W0row0 + lane + 32 * g);
            ull init = pack2(fmaf(tn, w, b), 0.0f);
#pragma unroll
            for (int r = 0; r < R4; r++) acc[r][g] = init;
        }
    }
    gemm_kp128<HID>(Wp0, aIn, acc, lane);
#pragma unroll
    for (int r = 0; r < R4; r++)
#pragma unroll
        for (int g = 0; g < 4; g++) {
            float2 v = unpack2(acc[r][g]);
            hS[r * MLPW + lane + 32 * g] = lipswish(v.x + v.y);
        }
    __syncwarp();

    {
#pragma unroll
        for (int g = 0; g < 4; g++) {
            ull init = pack2(__ldg(b1 + lane + 32 * g), 0.0f);
#pragma unroll
            for (int r = 0; r < R4; r++) acc[r][g] = init;
        }
    }
    gemm_kp128<MLPW>(Wp1, hS, acc, lane);
    __syncwarp();   // all lanes done reading h1 before in-place overwrite
#pragma unroll
    for (int r = 0; r < R4; r++)
#pragma unroll
        for (int g = 0; g < 4; g++) {
            float2 v = unpack2(acc[r][g]);
            hS[r * MLPW + lane + 32 * g] = lipswish(v.x + v.y);
        }
    __syncwarp();

    ull acc2[R4][2];
    {
#pragma unroll
        for (int g = 0; g < 2; g++) {
            ull init = pack2(__ldg(bo + lane + 32 * g), 0.0f);
#pragma unroll
            for (int r = 0; r < R4; r++) acc2[r][g] = init;
        }
    }
    gemm_kp64<MLPW>(Wpo, hS, acc2, lane);
#pragma unroll
    for (int r = 0; r < R4; r++)
#pragma unroll
        for (int j = 0; j < 2; j++) {
            float2 v = unpack2(acc2[r][j]);
            outv[r][j] = tanhf(v.x + v.y);
        }
}

// Drift warp: stage z into zc (reuses hD), then one pass of 4-rows readout.
__device__ __forceinline__ void readout_kp(
    const float zz[R4][2], float* __restrict__ zc,
    const float (*sRWt)[68], const float* __restrict__ sRB,
    float* __restrict__ out, int rowbase, int tIdx, float tval, int lane)
{
#pragma unroll
    for (int r = 0; r < R4; r++) {
        zc[r * HID + lane]      = zz[r][0];
        zc[r * HID + lane + 32] = zz[r][1];
    }
    __syncwarp();
    const int d = lane & 7;
    const int r = lane >> 3;
    float acc = sRB[d];
#pragma unroll
    for (int hb = 0; hb < HID / 4; hb++) {
        float4 zv = *reinterpret_cast<const float4*>(zc + r * HID + hb * 4);
        float4 wv = *reinterpret_cast<const float4*>(&sRWt[d][hb * 4]);
        acc = fmaf(zv.x, wv.x, acc);
        acc = fmaf(zv.y, wv.y, acc);
        acc = fmaf(zv.z, wv.z, acc);
        acc = fmaf(zv.w, wv.w, acc);
    }
    size_t base = ((size_t)(rowbase + r) * T_STEPS + tIdx) * (DOUT + 1);
    out[base + 1 + d] = acc;
    if (d == 0) out[base] = tval;
    __syncwarp();   // zc (hD) reads done before next MLP reuses it
}

__global__ void __launch_bounds__(NWARPS * 32, 1)
sde_kernel(const float* __restrict__ ts,
           const float* __restrict__ dW,
           const float* __restrict__ dW0, const float* __restrict__ db0,
           const float* __restrict__ db1, const float* __restrict__ dbo,
           const float* __restrict__ fW0, const float* __restrict__ fb0,
           const float* __restrict__ fb1, const float* __restrict__ fbo,
           const float* __restrict__ RW, const float* __restrict__ rb,
           float* __restrict__ out)
{
    extern __shared__ char dyn[];
    QShm* Q = reinterpret_cast<QShm*>(dyn);
    float (*sRWt)[68] = reinterpret_cast<float(*)[68]>(dyn + P8 * sizeof(QShm));
    float* sRB = reinterpret_cast<float*>(dyn + P8 * sizeof(QShm) + DOUT * 68 * sizeof(float));

    const int tid  = threadIdx.x;
    const int w    = tid >> 5;
    const int lane = tid & 31;
    const int q    = w >> 1;
    const bool isDrift = (w & 1) == 0;
    QShm& S = Q[q];
    float* hS = isDrift ? &S.hD[0][0] : &S.hF[0][0];
    const int rowbase = (blockIdx.x * P8 + q) * R4;

    for (int i = tid; i < HID * DOUT; i += blockDim.x)
        sRWt[i & 7][i >> 3] = __ldg(RW + i);        // RW is (64, 8) row-major
    if (tid < DOUT) sRB[tid] = __ldg(rb + tid);

    const float t0  = __ldg(ts + 0);
    const float dt  = __ldg(ts + 1) - t0;
    const float sdt = sqrtf(dt);

    const float* Wp0 = isDrift ? wpD0 : wpF0;
    const float* Wp1 = isDrift ? wpD1 : wpF1;
    const float* Wpo = isDrift ? wpDo : wpFo;
    const float* W0r = isDrift ? dW0  : fW0;   // row 0 = t weights
    const float* b0  = isDrift ? db0  : fb0;
    const float* b1  = isDrift ? db1  : fb1;
    const float* bo  = isDrift ? dbo  : fbo;

    float zz[R4][2], zh[R4][2], ff[R4][2], gg[R4][2], res[R4][2];

    if (isDrift) {
#pragma unroll
        for (int r = 0; r < R4; r++) {
            zz[r][0] = zz[r][1] = 1.0f;
            zh[r][0] = zh[r][1] = 1.0f;
            S.aIn[r][lane]      = 1.0f;
            S.aIn[r][lane + 32] = 1.0f;
        }
    } else {
        // stage sqrt(dt)*dW for step 0 into buffer 0
#pragma unroll
        for (int r = 0; r < R4; r++) {
            float a = __ldg(dW + (size_t)(rowbase + r) * HID + lane);
            float b = __ldg(dW + (size_t)(rowbase + r) * HID + lane + 32);
            S.dwS[0][r][lane]      = a * sdt;
            S.dwS[0][r][lane + 32] = b * sdt;
        }
    }
    __syncthreads();   // sRWt + initial staging visible block-wide (once)

    // f0 / g0 at t = ts[0], x0 = ones
    mlp_kp(t0, Wp0, W0r, b0, Wp1, b1, Wpo, bo, &S.aIn[0][0], hS, res, lane);
    if (!isDrift) {
#pragma unroll
        for (int r = 0; r < R4; r++) {
            S.gEx[r][lane]      = res[r][0];
            S.gEx[r][lane + 32] = res[r][1];
        }
    }
    pair_sync(q);

    if (isDrift) {
#pragma unroll
        for (int r = 0; r < R4; r++) {
            ff[r][0] = res[r][0]; ff[r][1] = res[r][1];
            gg[r][0] = S.gEx[r][lane];
            gg[r][1] = S.gEx[r][lane + 32];
        }
        readout_kp(zz, &S.hD[0][0], sRWt, sRB, out, rowbase, 0, t0, lane); // z = ones
    }

    for (int n = 0; n < NSTEP; n++) {
        const float tn = __ldg(ts + n + 1);

        if (isDrift) {
            // zhat_{n+1} = 2z - zhat + f dt + g dw ; stage compact
#pragma unroll
            for (int r = 0; r < R4; r++) {
#pragma unroll
                for (int j = 0; j < 2; j++) {
                    float dw = S.dwS[n & 1][r][lane + 32 * j];
                    float t1 = fmaf(2.0f, zz[r][j], -zh[r][j]);
                    t1 = fmaf(ff[r][j], dt, t1);
                    zh[r][j] = fmaf(gg[r][j], dw, t1);
                    S.aIn[r][lane + 32 * j] = zh[r][j];
                }
            }
        }
        pair_sync(q);      // B1: aIn ready

        mlp_kp(tn, Wp0, W0r, b0, Wp1, b1, Wpo, bo, &S.aIn[0][0], hS, res, lane);

        if (!isDrift) {
#pragma unroll
            for (int r = 0; r < R4; r++) {
                S.gEx[r][lane]      = res[r][0];
                S.gEx[r][lane + 32] = res[r][1];
            }
            // stage next step's Brownian increments into the other buffer
            const int m = (n + 1 < NSTEP) ? (n + 1) : (NSTEP - 1);
#pragma unroll
            for (int r = 0; r < R4; r++) {
                float a = __ldg(dW + ((size_t)m * B_SZ + rowbase + r) * HID + lane);
                float b = __ldg(dW + ((size_t)m * B_SZ + rowbase + r) * HID + lane + 32);
                S.dwS[(n + 1) & 1][r][lane]      = a * sdt;
                S.dwS[(n + 1) & 1][r][lane + 32] = b * sdt;
            }
        }
        pair_sync(q);      // B2: gEx (and next dwS) ready

        if (isDrift) {
#pragma unroll
            for (int r = 0; r < R4; r++) {
#pragma unroll
                for (int j = 0; j < 2; j++) {
                    float gn = S.gEx[r][lane + 32 * j];
                    float dw = S.dwS[n & 1][r][lane + 32 * j];
                    float fn = res[r][j];
                    zz[r][j] = fmaf(0.5f * (ff[r][j] + fn), dt, zz[r][j]);
                    zz[r][j] = fmaf(0.5f * (gg[r][j] + gn), dw, zz[r][j]);
                    ff[r][j] = fn;
                    gg[r][j] = gn;
                }
            }
            readout_kp(zz, &S.hD[0][0], sRWt, sRB, out, rowbase, n + 1, tn, lane);
        }
    }
}

extern "C" void kernel_launch(void* const* d_in, const int* in_sizes, int n_in,
                              void* d_out, int out_size) {
    (void)in_sizes; (void)n_in; (void)out_size;
    const float* ts  = (const float*)d_in[0];
    // d_in[1] = batch_size (int32 scalar) — shapes are fixed constants here
    const float* dW  = (const float*)d_in[2];
    const float* dW0 = (const float*)d_in[3];
    const float* db0 = (const float*)d_in[4];
    const float* dW1 = (const float*)d_in[5];
    const float* db1 = (const float*)d_in[6];
    const float* dWo = (const float*)d_in[7];
    const float* dbo = (const float*)d_in[8];
    const float* fW0 = (const float*)d_in[9];
    const float* fb0 = (const float*)d_in[10];
    const float* fW1 = (const float*)d_in[11];
    const float* fb1 = (const float*)d_in[12];
    const float* fWo = (const float*)d_in[13];
    const float* fbo = (const float*)d_in[14];
    const float* RW  = (const float*)d_in[15];
    const float* rb  = (const float*)d_in[16];
    float* out = (float*)d_out;

    pack_weights<<<256, 256>>>(dW0, dW1, dWo, fW0, fW1, fWo);

    const int smem = P8 * (int)sizeof(QShm) + DOUT * 68 * (int)sizeof(float) + 64;
    cudaFuncSetAttribute(sde_kernel, cudaFuncAttributeMaxDynamicSharedMemorySize, smem);

    sde_kernel<<<NCTA, NWARPS * 32, smem>>>(ts, dW,
                                            dW0, db0, db1, dbo,
                                            fW0, fb0, fb1, fbo,
                                            RW, rb, out);
}

// round 12
// speedup vs baseline: 1.3629x; 1.3596x over previous
#include <cuda_runtime.h>

namespace {
constexpr int T_STEPS = 256;
constexpr int B_SZ    = 4096;
constexpr int HID     = 64;
constexpr int MLPW    = 128;
constexpr int DOUT    = 8;
constexpr int RP      = 2;            // row-pairs per warp => 4 rows/warp
constexpr int NWARPS  = 14;           // 7 drift/diff warp-pairs per CTA
constexpr int QP      = NWARPS / 2;   // warp-pairs per CTA
constexpr int NSTEP   = 255;
constexpr int NCTA    = 148;          // 148 * 7 * 4 = 4144 >= 4096; tail pairs idle
}

using ull = unsigned long long;

struct QShm {                     // one drift/diff warp-pair's staging
    ull aIn[RP][HID];             // zhat input, row-paired       (1 KB)
    ull hD [RP][MLPW];            // drift MLP scratch + readout  (2 KB)
    ull hF [RP][MLPW];            // diff MLP scratch             (2 KB)
    ull gEx[RP][HID];             // g exchange                   (1 KB)
    ull dwS[2][RP][HID];          // sqrt(dt)*dW double buffer    (2 KB)
};                                // 8192 B

__device__ __forceinline__ ull fma2(ull a, ull b, ull c) {
    ull d; asm("fma.rn.f32x2 %0, %1, %2, %3;" : "=l"(d) : "l"(a), "l"(b), "l"(c)); return d;
}
__device__ __forceinline__ ull add2(ull a, ull b) {
    ull d; asm("add.rn.f32x2 %0, %1, %2;" : "=l"(d) : "l"(a), "l"(b)); return d;
}
__device__ __forceinline__ ull mul2(ull a, ull b) {
    ull d; asm("mul.rn.f32x2 %0, %1, %2;" : "=l"(d) : "l"(a), "l"(b)); return d;
}
__device__ __forceinline__ ull splat2(float x) {
    ull d; unsigned u = __float_as_uint(x);
    asm("mov.b64 %0, {%1, %1};" : "=l"(d) : "r"(u)); return d;
}
__device__ __forceinline__ ull pack2(float lo, float hi) {
    ull d; unsigned a = __float_as_uint(lo), b = __float_as_uint(hi);
    asm("mov.b64 %0, {%1, %2};" : "=l"(d) : "r"(a), "r"(b)); return d;
}
__device__ __forceinline__ float2 unpack2(ull v) {
    float2 r; asm("mov.b64 {%0, %1}, %2;" : "=f"(r.x), "=f"(r.y) : "l"(v)); return r;
}
__device__ __forceinline__ float4 ldg4(const float* p){ return __ldg((const float4*)p); }
__device__ __forceinline__ float2 ldg2f(const float* p){ return __ldg((const float2*)p); }
__device__ __forceinline__ float lipswish(float x){
    float s = 1.0f / (1.0f + __expf(-x)); return 0.909f * x * s;
}
// pairwise barrier: the 2 warps (64 threads) of pair q only (IDs 1..7)
__device__ __forceinline__ void pair_sync(int q) {
    asm volatile("bar.sync %0, 64;" :: "r"(q + 1) : "memory");
}

// acc[p][c]: (row2p, row2p+1) for lane cols 4l..4l+3. aS row-paired, stride K.
template<int K>
__device__ __forceinline__ void gemm128_rp(const float* __restrict__ W,
                                           const ull* __restrict__ aS,
                                           ull acc[RP][4], int lane)
{
    const float* Wp = W + 4 * lane;
#pragma unroll 4
    for (int kb = 0; kb < K / 4; kb++) {
        ulonglong2 a0[RP], a1[RP];
#pragma unroll
        for (int p = 0; p < RP; p++) {
            a0[p] = *reinterpret_cast<const ulonglong2*>(aS + p * K + kb * 4);
            a1[p] = *reinterpret_cast<const ulonglong2*>(aS + p * K + kb * 4 + 2);
        }
        float4 wv[4];
#pragma unroll
        for (int kk = 0; kk < 4; kk++)
            wv[kk] = ldg4(Wp + (kb * 4 + kk) * MLPW);
#pragma unroll
        for (int kk = 0; kk < 4; kk++) {
            ull w0 = splat2(wv[kk].x), w1 = splat2(wv[kk].y);
            ull w2 = splat2(wv[kk].z), w3 = splat2(wv[kk].w);
#pragma unroll
            for (int p = 0; p < RP; p++) {
                ull av = (kk == 0) ? a0[p].x : (kk == 1) ? a0[p].y
                       : (kk == 2) ? a1[p].x : a1[p].y;
                acc[p][0] = fma2(av, w0, acc[p][0]);
                acc[p][1] = fma2(av, w1, acc[p][1]);
                acc[p][2] = fma2(av, w2, acc[p][2]);
                acc[p][3] = fma2(av, w3, acc[p][3]);
            }
        }
    }
}

// N=64 output layer: lane cols 2l..2l+1, acc[p][j].
template<int K>
__device__ __forceinline__ void gemm64_rp(const float* __restrict__ W,
                                          const ull* __restrict__ aS,
                                          ull acc[RP][2], int lane)
{
    const float* Wp = W + 2 * lane;
#pragma unroll 4
    for (int kb = 0; kb < K / 4; kb++) {
        ulonglong2 a0[RP], a1[RP];
#pragma unroll
        for (int p = 0; p < RP; p++) {
            a0[p] = *reinterpret_cast<const ulonglong2*>(aS + p * K + kb * 4);
            a1[p] = *reinterpret_cast<const ulonglong2*>(aS + p * K + kb * 4 + 2);
        }
        float2 wv[4];
#pragma unroll
        for (int kk = 0; kk < 4; kk++)
            wv[kk] = ldg2f(Wp + (kb * 4 + kk) * HID);
#pragma unroll
        for (int kk = 0; kk < 4; kk++) {
            ull w0 = splat2(wv[kk].x), w1 = splat2(wv[kk].y);
#pragma unroll
            for (int p = 0; p < RP; p++) {
                ull av = (kk == 0) ? a0[p].x : (kk == 1) ? a0[p].y
                       : (kk == 2) ? a1[p].x : a1[p].y;
                acc[p][0] = fma2(av, w0, acc[p][0]);
                acc[p][1] = fma2(av, w1, acc[p][1]);
            }
        }
    }
}

__device__ __forceinline__ void mlp_rp(
    float tn,
    const float* __restrict__ W0, const float* __restrict__ b0,
    const float* __restrict__ W1, const float* __restrict__ b1,
    const float* __restrict__ Wo, const float* __restrict__ bo,
    const ull* __restrict__ aIn, ull* __restrict__ hS,
    ull out[RP][2], int lane)
{
    ull acc[RP][4];
    {   // bias + t * W0_row0 (same for both packed rows -> splat)
        float4 bv = ldg4(b0 + 4 * lane);
        float4 w0 = ldg4(W0 + 4 * lane);
        ull i0 = splat2(fmaf(tn, w0.x, bv.x));
        ull i1 = splat2(fmaf(tn, w0.y, bv.y));
        ull i2 = splat2(fmaf(tn, w0.z, bv.z));
        ull i3 = splat2(fmaf(tn, w0.w, bv.w));
#pragma unroll
        for (int p = 0; p < RP; p++) {
            acc[p][0] = i0; acc[p][1] = i1; acc[p][2] = i2; acc[p][3] = i3;
        }
    }
    gemm128_rp<HID>(W0 + MLPW, aIn, acc, lane);   // rows 1..64 of W0
#pragma unroll
    for (int p = 0; p < RP; p++) {
        ulonglong2 s0, s1;
        { float2 v = unpack2(acc[p][0]); s0.x = pack2(lipswish(v.x), lipswish(v.y)); }
        { float2 v = unpack2(acc[p][1]); s0.y = pack2(lipswish(v.x), lipswish(v.y)); }
        { float2 v = unpack2(acc[p][2]); s1.x = pack2(lipswish(v.x), lipswish(v.y)); }
        { float2 v = unpack2(acc[p][3]); s1.y = pack2(lipswish(v.x), lipswish(v.y)); }
        *reinterpret_cast<ulonglong2*>(hS + p * MLPW + 4 * lane)     = s0;
        *reinterpret_cast<ulonglong2*>(hS + p * MLPW + 4 * lane + 2) = s1;
    }
    __syncwarp();

    {
        float4 bv = ldg4(b1 + 4 * lane);
        ull i0 = splat2(bv.x), i1 = splat2(bv.y), i2 = splat2(bv.z), i3 = splat2(bv.w);
#pragma unroll
        for (int p = 0; p < RP; p++) {
            acc[p][0] = i0; acc[p][1] = i1; acc[p][2] = i2; acc[p][3] = i3;
        }
    }
    gemm128_rp<MLPW>(W1, hS, acc, lane);
    __syncwarp();   // all lanes done reading h1 before in-place overwrite
#pragma unroll
    for (int p = 0; p < RP; p++) {
        ulonglong2 s0, s1;
        { float2 v = unpack2(acc[p][0]); s0.x = pack2(lipswish(v.x), lipswish(v.y)); }
        { float2 v = unpack2(acc[p][1]); s0.y = pack2(lipswish(v.x), lipswish(v.y)); }
        { float2 v = unpack2(acc[p][2]); s1.x = pack2(lipswish(v.x), lipswish(v.y)); }
        { float2 v = unpack2(acc[p][3]); s1.y = pack2(lipswish(v.x), lipswish(v.y)); }
        *reinterpret_cast<ulonglong2*>(hS + p * MLPW + 4 * lane)     = s0;
        *reinterpret_cast<ulonglong2*>(hS + p * MLPW + 4 * lane + 2) = s1;
    }
    __syncwarp();

    ull acc2[RP][2];
    {
        float2 bv = ldg2f(bo + 2 * lane);
        ull i0 = splat2(bv.x), i1 = splat2(bv.y);
#pragma unroll
        for (int p = 0; p < RP; p++) { acc2[p][0] = i0; acc2[p][1] = i1; }
    }
    gemm64_rp<MLPW>(Wo, hS, acc2, lane);
#pragma unroll
    for (int p = 0; p < RP; p++) {
#pragma unroll
        for (int j = 0; j < 2; j++) {
            float2 v = unpack2(acc2[p][j]);
            out[p][j] = pack2(tanhf(v.x), tanhf(v.y));
        }
    }
}

// Drift warp only. Unpacks row-paired z into compact zc (reuses hD), then
// lane (r = lane>>3, d = lane&7) computes readout for 4 rows.
__device__ __forceinline__ void readout_rp(
    const ull z[RP][2], float* __restrict__ zc,
    const float (*sRWt)[68], const float* __restrict__ sRB,
    float* __restrict__ out, int rowbase, int tIdx, float tval, int lane)
{
#pragma unroll
    for (int p = 0; p < RP; p++) {
        float2 v0 = unpack2(z[p][0]);     // (row2p_c0, row2p+1_c0)
        float2 v1 = unpack2(z[p][1]);
        *reinterpret_cast<float2*>(zc + (2 * p) * HID + 2 * lane)     = make_float2(v0.x, v1.x);
        *reinterpret_cast<float2*>(zc + (2 * p + 1) * HID + 2 * lane) = make_float2(v0.y, v1.y);
    }
    __syncwarp();
    const int d = lane & 7;
    const int r = lane >> 3;
    float acc = sRB[d];
#pragma unroll
    for (int hb = 0; hb < HID / 4; hb++) {
        float4 zv = *reinterpret_cast<const float4*>(zc + r * HID + hb * 4);
        float4 wv = *reinterpret_cast<const float4*>(&sRWt[d][hb * 4]);
        acc = fmaf(zv.x, wv.x, acc);
        acc = fmaf(zv.y, wv.y, acc);
        acc = fmaf(zv.z, wv.z, acc);
        acc = fmaf(zv.w, wv.w, acc);
    }
    size_t base = ((size_t)(rowbase + r) * T_STEPS + tIdx) * (DOUT + 1);
    out[base + 1 + d] = acc;
    if (d == 0) out[base] = tval;
    __syncwarp();   // zc (hD) reads done before next MLP overwrites it
}

__global__ void __launch_bounds__(NWARPS * 32, 1)
sde_kernel(const float* __restrict__ ts,
           const float* __restrict__ dW,
           const float* __restrict__ dW0, const float* __restrict__ db0,
           const float* __restrict__ dW1, const float* __restrict__ db1,
           const float* __restrict__ dWo, const float* __restrict__ dbo,
           const float* __restrict__ fW0, const float* __restrict__ fb0,
           const float* __restrict__ fW1, const float* __restrict__ fb1,
           const float* __restrict__ fWo, const float* __restrict__ fbo,
           const float* __restrict__ RW, const float* __restrict__ rb,
           float* __restrict__ out)
{
    extern __shared__ char dyn[];
    QShm* Q = reinterpret_cast<QShm*>(dyn);
    float (*sRWt)[68] = reinterpret_cast<float(*)[68]>(dyn + QP * sizeof(QShm));
    float* sRB = reinterpret_cast<float*>(dyn + QP * sizeof(QShm) + DOUT * 68 * sizeof(float));

    const int tid  = threadIdx.x;
    const int w    = tid >> 5;
    const int lane = tid & 31;
    const int q    = w >> 1;
    const bool isDrift = (w & 1) == 0;
    QShm& S = Q[q];
    ull* hS = isDrift ? &S.hD[0][0] : &S.hF[0][0];
    const int rowbase = (blockIdx.x * QP + q) * (2 * RP);

    for (int i = tid; i < HID * DOUT; i += blockDim.x)
        sRWt[i & 7][i >> 3] = __ldg(RW + i);        // RW is (64, 8) row-major
    if (tid < DOUT) sRB[tid] = __ldg(rb + tid);

    const float t0  = __ldg(ts + 0);
    const float dt  = __ldg(ts + 1) - t0;
    const float sdt = sqrtf(dt);
    const ull dt2   = splat2(dt);
    const ull hdt2  = splat2(0.5f * dt);
    const ull half2 = splat2(0.5f);
    const ull two2  = splat2(2.0f);
    const ull one2  = splat2(1.0f);
    constexpr ull SGN2 = 0x8000000080000000ULL;

    const float* W0 = isDrift ? dW0 : fW0; const float* b0 = isDrift ? db0 : fb0;
    const float* W1 = isDrift ? dW1 : fW1; const float* b1 = isDrift ? db1 : fb1;
    const float* Wo = isDrift ? dWo : fWo; const float* bo = isDrift ? dbo : fbo;

    ull z[RP][2], zh[RP][2], fq[RP][2], g[RP][2], res[RP][2];

    __syncthreads();   // sRWt visible block-wide (before any early exit)

    if (rowbase >= B_SZ) return;   // tail pairs (48 of 4144 row-slots) idle

    if (isDrift) {
#pragma unroll
        for (int p = 0; p < RP; p++) {
            z[p][0] = z[p][1] = one2;
            zh[p][0] = zh[p][1] = one2;
            ulonglong2 o; o.x = one2; o.y = one2;
            *reinterpret_cast<ulonglong2*>(&S.aIn[p][2 * lane]) = o;
        }
    } else {
        // stage sqrt(dt)*dW for step 0 into buffer 0
#pragma unroll
        for (int p = 0; p < RP; p++) {
            float2 a = ldg2f(dW + (size_t)(rowbase + 2 * p)     * HID + 2 * lane);
            float2 b = ldg2f(dW + (size_t)(rowbase + 2 * p + 1) * HID + 2 * lane);
            ulonglong2 v;
            v.x = pack2(a.x * sdt, b.x * sdt);
            v.y = pack2(a.y * sdt, b.y * sdt);
            *reinterpret_cast<ulonglong2*>(&S.dwS[0][p][2 * lane]) = v;
        }
    }
    pair_sync(q);      // initial aIn / dwS staging visible within the pair

    // f0 / g0 at t = ts[0], x0 = ones
    mlp_rp(t0, W0, b0, W1, b1, Wo, bo, &S.aIn[0][0], hS, res, lane);
    if (!isDrift) {
#pragma unroll
        for (int p = 0; p < RP; p++) {
            ulonglong2 v; v.x = res[p][0]; v.y = res[p][1];
            *reinterpret_cast<ulonglong2*>(&S.gEx[p][2 * lane]) = v;
        }
    }
    pair_sync(q);

    if (isDrift) {
#pragma unroll
        for (int p = 0; p < RP; p++) {
            fq[p][0] = res[p][0]; fq[p][1] = res[p][1];
            ulonglong2 v = *reinterpret_cast<const ulonglong2*>(&S.gEx[p][2 * lane]);
            g[p][0] = v.x; g[p][1] = v.y;
        }
        readout_rp(z, reinterpret_cast<float*>(&S.hD[0][0]), sRWt, sRB,
                   out, rowbase, 0, t0, lane);   // z = ones
    }

    for (int n = 0; n < NSTEP; n++) {
        const float tn = __ldg(ts + n + 1);

        if (isDrift) {
            // zhat_{n+1} = 2z - zhat + f dt + g dw ; stage row-paired
#pragma unroll
            for (int p = 0; p < RP; p++) {
                ulonglong2 dwv = *reinterpret_cast<const ulonglong2*>(&S.dwS[n & 1][p][2 * lane]);
                ull dwp[2] = { dwv.x, dwv.y };
#pragma unroll
                for (int j = 0; j < 2; j++) {
                    ull t1 = fma2(two2, z[p][j], zh[p][j] ^ SGN2);
                    t1 = fma2(fq[p][j], dt2, t1);
                    zh[p][j] = fma2(g[p][j], dwp[j], t1);
                }
                ulonglong2 o; o.x = zh[p][0]; o.y = zh[p][1];
                *reinterpret_cast<ulonglong2*>(&S.aIn[p][2 * lane]) = o;
            }
        }
        pair_sync(q);      // B1: aIn ready

        mlp_rp(tn, W0, b0, W1, b1, Wo, bo, &S.aIn[0][0], hS, res, lane);

        if (!isDrift) {
#pragma unroll
            for (int p = 0; p < RP; p++) {
                ulonglong2 v; v.x = res[p][0]; v.y = res[p][1];
                *reinterpret_cast<ulonglong2*>(&S.gEx[p][2 * lane]) = v;
            }
            // stage next step's Brownian increments into the other buffer
            const int m = (n + 1 < NSTEP) ? (n + 1) : (NSTEP - 1);
#pragma unroll
            for (int p = 0; p < RP; p++) {
                float2 a = ldg2f(dW + ((size_t)m * B_SZ + rowbase + 2 * p)     * HID + 2 * lane);
                float2 b = ldg2f(dW + ((size_t)m * B_SZ + rowbase + 2 * p + 1) * HID + 2 * lane);
                ulonglong2 v;
                v.x = pack2(a.x * sdt, b.x * sdt);
                v.y = pack2(a.y * sdt, b.y * sdt);
                *reinterpret_cast<ulonglong2*>(&S.dwS[(n + 1) & 1][p][2 * lane]) = v;
            }
        }
        pair_sync(q);      // B2: gEx (and next dwS) ready

        if (isDrift) {
#pragma unroll
            for (int p = 0; p < RP; p++) {
                ulonglong2 gv = *reinterpret_cast<const ulonglong2*>(&S.gEx[p][2 * lane]);
                ulonglong2 dwv = *reinterpret_cast<const ulonglong2*>(&S.dwS[n & 1][p][2 * lane]);
                ull gn[2] = { gv.x, gv.y };
                ull dwp[2] = { dwv.x, dwv.y };
#pragma unroll
                for (int j = 0; j < 2; j++) {
                    ull s1 = add2(fq[p][j], res[p][j]);
                    z[p][j] = fma2(s1, hdt2, z[p][j]);
                    ull s2 = mul2(add2(g[p][j], gn[j]), half2);
                    z[p][j] = fma2(s2, dwp[j], z[p][j]);
                    fq[p][j] = res[p][j];
                    g[p][j]  = gn[j];
                }
            }
            readout_rp(z, reinterpret_cast<float*>(&S.hD[0][0]), sRWt, sRB,
                       out, rowbase, n + 1, tn, lane);
        }
    }
}

extern "C" void kernel_launch(void* const* d_in, const int* in_sizes, int n_in,
                              void* d_out, int out_size) {
    (void)in_sizes; (void)n_in; (void)out_size;
    const float* ts  = (const float*)d_in[0];
    // d_in[1] = batch_size (int32 scalar) — shapes are fixed constants here
    const float* dW  = (const float*)d_in[2];
    const float* dW0 = (const float*)d_in[3];
    const float* db0 = (const float*)d_in[4];
    const float* dW1 = (const float*)d_in[5];
    const float* db1 = (const float*)d_in[6];
    const float* dWo = (const float*)d_in[7];
    const float* dbo = (const float*)d_in[8];
    const float* fW0 = (const float*)d_in[9];
    const float* fb0 = (const float*)d_in[10];
    const float* fW1 = (const float*)d_in[11];
    const float* fb1 = (const float*)d_in[12];
    const float* fWo = (const float*)d_in[13];
    const float* fbo = (const float*)d_in[14];
    const float* RW  = (const float*)d_in[15];
    const float* rb  = (const float*)d_in[16];
    float* out = (float*)d_out;

    const int smem = QP * (int)sizeof(QShm) + DOUT * 68 * (int)sizeof(float) + 64;
    cudaFuncSetAttribute(sde_kernel, cudaFuncAttributeMaxDynamicSharedMemorySize, smem);

    sde_kernel<<<NCTA, NWARPS * 32, smem>>>(ts, dW,
                                            dW0, db0, dW1, db1, dWo, dbo,
                                            fW0, fb0, fW1, fb1, fWo, fbo,
                                            RW, rb, out);
}